// round 15
// baseline (speedup 1.0000x reference)
#include <cuda_runtime.h>
#include <cuda_bf16.h>
#include <cuda_fp16.h>
#include <cstdint>

// Problem constants
constexpr int NN = 50000;    // nodes
constexpr int NE = 800000;   // edges
constexpr int NG = 1024;     // graphs
constexpr int H  = 128;      // hidden / node feature dim
constexpr int DS = 768;      // smiles dim
constexpr int NC = 12;       // classes

constexpr int SCAN_B  = 256;
constexpr int SCAN_NB = (NN + SCAN_B - 1) / SCAN_B;   // 196

// Scratch (device globals; no allocation allowed)
__device__ __half g_hsH[(size_t)NN * H];   // fp16 gather table (both layers)
__device__ __half g_sumH[(size_t)NN * H];  // layer-1 aggregate sum (fp16)
__device__ float  g_dinv[NN];
__device__ int    g_edeg[NN];              // edge-only in-degree
__device__ int    g_off[NN + 1];           // CSR offsets (by dst)
__device__ int    g_cursor[NN];
__device__ int    g_csr[NE];               // src ids grouped by dst
__device__ int    g_blocksum[SCAN_B];
__device__ int    g_blockoff[SCAN_B];
__device__ float  g_gsum[NG * H];
__device__ int    g_cnt[NG];

// ---------------------------------------------------------------------------
// Helpers
// ---------------------------------------------------------------------------
__device__ __forceinline__ float to_tf32(float x) {
    unsigned r;  // cvt to tf32 requires a .b32 destination register
    asm("cvt.rna.tf32.f32 %0, %1;" : "=r"(r) : "f"(x));
    return __uint_as_float(r);
}
__device__ __forceinline__ void mma_tf32(float& d0, float& d1, float& d2, float& d3,
                                         float a0, float a1, float a2, float a3,
                                         float b0, float b1) {
    asm volatile(
        "mma.sync.aligned.m16n8k8.row.col.f32.tf32.tf32.f32 "
        "{%0,%1,%2,%3}, {%4,%5,%6,%7}, {%8,%9}, {%0,%1,%2,%3};"
        : "+f"(d0), "+f"(d1), "+f"(d2), "+f"(d3)
        : "r"(__float_as_uint(a0)), "r"(__float_as_uint(a1)),
          "r"(__float_as_uint(a2)), "r"(__float_as_uint(a3)),
          "r"(__float_as_uint(b0)), "r"(__float_as_uint(b1)));
}
__device__ __forceinline__ void red_add_v4(float* p, float4 v) {
    asm volatile("red.global.add.v4.f32 [%0], {%1, %2, %3, %4};"
                 :: "l"(p), "f"(v.x), "f"(v.y), "f"(v.z), "f"(v.w)
                 : "memory");
}
// Accumulate 4 halves (as uint2) into a float4 accumulator.
__device__ __forceinline__ void acc_h4(float4& a, uint2 u) {
    __half2 h0 = *reinterpret_cast<__half2*>(&u.x);
    __half2 h1 = *reinterpret_cast<__half2*>(&u.y);
    float2 f0 = __half22float2(h0);
    float2 f1 = __half22float2(h1);
    a.x += f0.x; a.y += f0.y; a.z += f1.x; a.w += f1.y;
}

// ---------------------------------------------------------------------------
// K0: zero/init
// ---------------------------------------------------------------------------
__global__ void prep_zero_kernel(int* __restrict__ edeg, int* __restrict__ cnt,
                                 float* __restrict__ gsum, int* __restrict__ off) {
    int i = blockIdx.x * blockDim.x + threadIdx.x;
    if (i < NN) edeg[i] = 0;
    if (i < NG) cnt[i] = 0;
    if (i < NG * H) gsum[i] = 0.0f;
    if (i == 0) off[NN] = NE;
}

// ---------------------------------------------------------------------------
// K1: in-degree (edges only) + node counts per graph
// ---------------------------------------------------------------------------
__global__ void count_kernel(const int* __restrict__ dst, const int* __restrict__ batch,
                             int* __restrict__ edeg, int* __restrict__ cnt) {
    int i = blockIdx.x * blockDim.x + threadIdx.x;
    if (i < NE) atomicAdd(&edeg[dst[i]], 1);
    if (i < NN) atomicAdd(&cnt[batch[i]], 1);
}

// ---------------------------------------------------------------------------
// Scan stage 1: per-block sums of edeg
// ---------------------------------------------------------------------------
__global__ __launch_bounds__(SCAN_B)
void scan1_kernel(const int* __restrict__ edeg, int* __restrict__ blocksum) {
    __shared__ int sh[SCAN_B];
    int t = threadIdx.x;
    int i = blockIdx.x * SCAN_B + t;
    sh[t] = (i < NN) ? edeg[i] : 0;
    __syncthreads();
    for (int d = SCAN_B / 2; d > 0; d >>= 1) {
        if (t < d) sh[t] += sh[t + d];
        __syncthreads();
    }
    if (t == 0) blocksum[blockIdx.x] = sh[0];
}

// ---------------------------------------------------------------------------
// Scan stage 2: single-block exclusive scan of block sums
// ---------------------------------------------------------------------------
__global__ __launch_bounds__(SCAN_B)
void scan2_kernel(const int* __restrict__ blocksum, int* __restrict__ blockoff) {
    __shared__ int sh[SCAN_B];
    int t = threadIdx.x;
    int v = (t < SCAN_NB) ? blocksum[t] : 0;
    sh[t] = v;
    __syncthreads();
    for (int d = 1; d < SCAN_B; d <<= 1) {
        int add = (t >= d) ? sh[t - d] : 0;
        __syncthreads();
        sh[t] += add;
        __syncthreads();
    }
    blockoff[t] = sh[t] - v;   // exclusive
}

// ---------------------------------------------------------------------------
// Scan stage 3: per-element exclusive offsets; init cursor; dinv (folded).
// ---------------------------------------------------------------------------
__global__ __launch_bounds__(SCAN_B)
void scan3_kernel(const int* __restrict__ edeg, const int* __restrict__ blockoff,
                  int* __restrict__ off, int* __restrict__ cursor,
                  float* __restrict__ dinv) {
    __shared__ int wsum[8], wbase[8];
    int t = threadIdx.x;
    int lane = t & 31, wid = t >> 5;
    int i = blockIdx.x * SCAN_B + t;
    int v = (i < NN) ? edeg[i] : 0;
    int x = v;
#pragma unroll
    for (int d = 1; d < 32; d <<= 1) {
        int y = __shfl_up_sync(0xffffffff, x, d);
        if (lane >= d) x += y;
    }
    if (lane == 31) wsum[wid] = x;
    __syncthreads();
    if (t == 0) {
        int run = 0;
#pragma unroll
        for (int k = 0; k < 8; k++) { wbase[k] = run; run += wsum[k]; }
    }
    __syncthreads();
    if (i < NN) {
        int e = blockoff[blockIdx.x] + wbase[wid] + (x - v);
        off[i] = e;
        cursor[i] = e;
        dinv[i] = rsqrtf((float)(v + 1));   // self-loop included
    }
}

// ---------------------------------------------------------------------------
// K3: scatter edges into CSR (grouped by dst)
// ---------------------------------------------------------------------------
__global__ void scatter_kernel(const int* __restrict__ src, const int* __restrict__ dst,
                               int* __restrict__ cursor, int* __restrict__ csr) {
    int i = blockIdx.x * blockDim.x + threadIdx.x;
    if (i >= NE) return;
    int d = dst[i];
    int p = atomicAdd(&cursor[d], 1);
    csr[p] = src[i];
}

// ---------------------------------------------------------------------------
// Single-wave tf32 tensor-core GEMM, 192-row tiles (one tile per CTA):
//   hsH[M,128] = fp16( dinv[row] * (T(A)[M,128] @ W[128,128]) )
//   mode 0: A is fp32; T(a) = a
//   mode 1: A is fp16 (layer-1 sums); T(a) = relu(biasIn[k] + dinv[row]*a)
// 256 thr (8 warps); warp wi owns cols wi*16..+15, 12 m-tiles of 16 rows.
// W tf32-resident [128][136]; X staged in 32-k chunks [192][36].
// ---------------------------------------------------------------------------
constexpr int TROWS = 192;
constexpr int WS_STRIDE = 136;
constexpr int XS_STRIDE = 36;
constexpr int GEMM_SMEM = 128 * WS_STRIDE * 4 + TROWS * XS_STRIDE * 4;  // 97280
constexpr int GEMM_TILES = (NN + TROWS - 1) / TROWS;      // 261

__global__ __launch_bounds__(256, 2)
void gemm_tc_kernel(const void* __restrict__ A, const float* __restrict__ W,
                    const float* __restrict__ dinv, const float* __restrict__ biasIn,
                    __half* __restrict__ outH, int M, int mode)
{
    extern __shared__ char smem_raw[];
    float* Wsm = (float*)smem_raw;                         // [128][136]
    float* Xs  = (float*)(smem_raw + 128 * WS_STRIDE * 4); // [192][36]

    const int tid  = threadIdx.x;
    const int lane = tid & 31;
    const int wi   = tid >> 5;        // warp id 0..7
    const int n0   = wi * 16;         // this warp's col base
    const int lq   = lane >> 2;       // lane/4: 0..7
    const int lr   = lane & 3;        // lane%4: 0..3

    // Stage W (tf32): 4096 float4 loads, 16 per thread.
#pragma unroll
    for (int i = 0; i < 16; i++) {
        int li = tid + i * 256;       // 0..4095
        int k  = li >> 5;             // 0..127
        int c4 = li & 31;             // 0..31
        float4 v = __ldg((const float4*)W + li);
        float* wp = Wsm + k * WS_STRIDE + c4 * 4;
        wp[0] = to_tf32(v.x); wp[1] = to_tf32(v.y);
        wp[2] = to_tf32(v.z); wp[3] = to_tf32(v.w);
    }

    for (int tile = blockIdx.x; tile < GEMM_TILES; tile += gridDim.x) {
        const int row0 = tile * TROWS;

        float acc[12][2][4];
#pragma unroll
        for (int mt = 0; mt < 12; mt++)
#pragma unroll
            for (int nt = 0; nt < 2; nt++)
#pragma unroll
                for (int c = 0; c < 4; c++) acc[mt][nt][c] = 0.0f;

        for (int chunk = 0; chunk < 4; chunk++) {
            const int k0 = chunk * 32;
            __syncthreads();   // Xs reusable / publishes W on first pass
            // Stage X chunk: 192 rows x 32 k = 1536 vec4 loads, 6/thread.
#pragma unroll
            for (int i = 0; i < 6; i++) {
                int li = tid + i * 256;    // 0..1535
                int r  = li >> 3;          // 0..191
                int c4 = li & 7;           // 0..7
                int gr = row0 + r;
                float4 v = make_float4(0.f, 0.f, 0.f, 0.f);
                if (gr < M) {
                    if (mode == 0) {
                        v = __ldg((const float4*)((const float*)A +
                                  (size_t)gr * 128 + k0) + c4);
                    } else {
                        // fp16 source: 4 halves per uint2
                        uint2 u = __ldg((const uint2*)((const __half*)A +
                                  (size_t)gr * 128 + k0) + c4);
                        __half2 h0 = *reinterpret_cast<__half2*>(&u.x);
                        __half2 h1 = *reinterpret_cast<__half2*>(&u.y);
                        float2 f0 = __half22float2(h0);
                        float2 f1 = __half22float2(h1);
                        float di = __ldg(&dinv[gr]);
                        float4 bb = __ldg((const float4*)(biasIn + k0) + c4);
                        v.x = fmaxf(bb.x + di * f0.x, 0.f);
                        v.y = fmaxf(bb.y + di * f0.y, 0.f);
                        v.z = fmaxf(bb.z + di * f1.x, 0.f);
                        v.w = fmaxf(bb.w + di * f1.y, 0.f);
                    }
                }
                float* xr = Xs + r * XS_STRIDE + c4 * 4;
                xr[0] = to_tf32(v.x); xr[1] = to_tf32(v.y);
                xr[2] = to_tf32(v.z); xr[3] = to_tf32(v.w);
            }
            __syncthreads();

#pragma unroll
            for (int ks = 0; ks < 4; ks++) {
                const int kb = k0 + ks * 8;      // absolute k for W
                const int kx = ks * 8;           // k within X chunk
                float b[2][2];
#pragma unroll
                for (int nt = 0; nt < 2; nt++) {
                    int nc = n0 + nt * 8 + lq;
                    b[nt][0] = Wsm[(kb + lr) * WS_STRIDE + nc];
                    b[nt][1] = Wsm[(kb + 4 + lr) * WS_STRIDE + nc];
                }
#pragma unroll
                for (int mt = 0; mt < 12; mt++) {
                    int rbase = mt * 16;
                    float a0 = Xs[(rbase + lq) * XS_STRIDE + kx + lr];
                    float a1 = Xs[(rbase + lq + 8) * XS_STRIDE + kx + lr];
                    float a2 = Xs[(rbase + lq) * XS_STRIDE + kx + lr + 4];
                    float a3 = Xs[(rbase + lq + 8) * XS_STRIDE + kx + lr + 4];
                    mma_tf32(acc[mt][0][0], acc[mt][0][1], acc[mt][0][2], acc[mt][0][3],
                             a0, a1, a2, a3, b[0][0], b[0][1]);
                    mma_tf32(acc[mt][1][0], acc[mt][1][1], acc[mt][1][2], acc[mt][1][3],
                             a0, a1, a2, a3, b[1][0], b[1][1]);
                }
            }
        }

        // Epilogue: scale rows by dinv, store fp16 pairs.
#pragma unroll
        for (int mt = 0; mt < 12; mt++) {
            int r1 = row0 + mt * 16 + lq;
            int r2 = r1 + 8;
            float d1 = (r1 < M) ? __ldg(&dinv[r1]) : 0.f;
            float d2 = (r2 < M) ? __ldg(&dinv[r2]) : 0.f;
#pragma unroll
            for (int nt = 0; nt < 2; nt++) {
                int col = n0 + nt * 8 + lr * 2;
                if (r1 < M)
                    *(__half2*)(outH + (size_t)r1 * 128 + col) =
                        __floats2half2_rn(acc[mt][nt][0] * d1, acc[mt][nt][1] * d1);
                if (r2 < M)
                    *(__half2*)(outH + (size_t)r2 * 128 + col) =
                        __floats2half2_rn(acc[mt][nt][2] * d2, acc[mt][nt][3] * d2);
            }
        }
    }
}

// ---------------------------------------------------------------------------
// Aggregate: one warp per node, fp16 gather (256B/row), fp32 accumulation.
// sum = hs[n] + sum_{src in CSR[n]} hs[src]; lane owns cols lane*4..lane*4+3.
//   mode 0: write fp16 sum to outSum (layer-1 path; GEMM2 re-reads fp16)
//   mode 1: v = relu(bg2 + dinv[n]*sum); red_add to gsum[batch[n]]  (fused pool)
// ---------------------------------------------------------------------------
__global__ __launch_bounds__(256)
void agg_kernel(const uint2* __restrict__ hsv, const int* __restrict__ off,
                const int* __restrict__ csr, const float* __restrict__ dinv,
                const float* __restrict__ bias, const int* __restrict__ batch,
                uint2* __restrict__ outSum, float* __restrict__ gsum, int mode)
{
    int w = (blockIdx.x * blockDim.x + threadIdx.x) >> 5;
    if (w >= NN) return;
    int lane = threadIdx.x & 31;
    int o0 = __ldg(&off[w]);
    int o1 = __ldg(&off[w + 1]);

    float4 acc0 = make_float4(0.f, 0.f, 0.f, 0.f);
    float4 acc1 = make_float4(0.f, 0.f, 0.f, 0.f);
    acc_h4(acc0, __ldg(&hsv[(size_t)w * 32 + lane]));   // self-loop term

    int j = o0;
    for (; j + 4 <= o1; j += 4) {
        int s0 = __ldg(&csr[j]);
        int s1 = __ldg(&csr[j + 1]);
        int s2 = __ldg(&csr[j + 2]);
        int s3 = __ldg(&csr[j + 3]);
        uint2 v0 = __ldg(&hsv[(size_t)s0 * 32 + lane]);
        uint2 v1 = __ldg(&hsv[(size_t)s1 * 32 + lane]);
        uint2 v2 = __ldg(&hsv[(size_t)s2 * 32 + lane]);
        uint2 v3 = __ldg(&hsv[(size_t)s3 * 32 + lane]);
        acc_h4(acc0, v0); acc_h4(acc1, v1); acc_h4(acc0, v2); acc_h4(acc1, v3);
    }
    for (; j < o1; j++) {
        int s = __ldg(&csr[j]);
        acc_h4(acc0, __ldg(&hsv[(size_t)s * 32 + lane]));
    }
    acc0.x += acc1.x; acc0.y += acc1.y; acc0.z += acc1.z; acc0.w += acc1.w;

    if (mode == 0) {
        __half2 h0 = __floats2half2_rn(acc0.x, acc0.y);
        __half2 h1 = __floats2half2_rn(acc0.z, acc0.w);
        uint2 o;
        o.x = *reinterpret_cast<unsigned*>(&h0);
        o.y = *reinterpret_cast<unsigned*>(&h1);
        outSum[(size_t)w * 32 + lane] = o;
    } else {
        float di = __ldg(&dinv[w]);
        float4 bb = __ldg((const float4*)bias + lane);
        acc0.x = fmaxf(bb.x + di * acc0.x, 0.f);
        acc0.y = fmaxf(bb.y + di * acc0.y, 0.f);
        acc0.z = fmaxf(bb.z + di * acc0.z, 0.f);
        acc0.w = fmaxf(bb.w + di * acc0.w, 0.f);
        int b = __ldg(&batch[w]);
        red_add_v4(gsum + (size_t)b * 128 + lane * 4, acc0);
    }
}

// ---------------------------------------------------------------------------
// Fused head: 16 graphs per block, 256 threads (thread j: col j&127,
// graph-half j>>7), dynamic smem. Halves Ws1/Ws2/Wf L2 traffic vs 8/block.
// ---------------------------------------------------------------------------
constexpr int FIN_G = 16;   // graphs per block
constexpr int FIN_SMEM = (FIN_G * DS + FIN_G * H + FIN_G * 2 * H + FIN_G * H) * 4;

__global__ __launch_bounds__(256)
void final_kernel(const float* __restrict__ smiles,
                  const float* __restrict__ Ws1, const float* __restrict__ bs1,
                  const float* __restrict__ Ws2, const float* __restrict__ bs2,
                  const float* __restrict__ Wf,  const float* __restrict__ bf,
                  const float* __restrict__ Wo,  const float* __restrict__ bo,
                  const float* __restrict__ gsum, const int* __restrict__ cnt,
                  float* __restrict__ out) {
    extern __shared__ float fsm[];
    float* sm   = fsm;                         // [16][DS]
    float* s1   = sm + FIN_G * DS;             // [16][H]
    float* comb = s1 + FIN_G * H;              // [16][2H]
    float* fz   = comb + FIN_G * 2 * H;        // [16][H]

    const int b0 = blockIdx.x * FIN_G;
    const int tid = threadIdx.x;
    const int col = tid & 127;
    const int g0 = (tid >> 7) * 8;             // graph offset: 0 or 8

    // cooperative smiles load: 16*768 floats = 3072 float4s, 12/thread
    const float4* sp = (const float4*)(smiles + (size_t)b0 * DS);
#pragma unroll
    for (int i = 0; i < 12; i++)
        ((float4*)sm)[tid + i * 256] = __ldg(sp + tid + i * 256);
    __syncthreads();

    float a[8];
#pragma unroll
    for (int g = 0; g < 8; g++) a[g] = 0.f;
#pragma unroll 4
    for (int k = 0; k < DS; k++) {
        float w = __ldg(&Ws1[(size_t)k * H + col]);
#pragma unroll
        for (int g = 0; g < 8; g++) a[g] += sm[(g0 + g) * DS + k] * w;
    }
    {
        float b1 = __ldg(&bs1[col]);
#pragma unroll
        for (int g = 0; g < 8; g++) s1[(g0 + g) * H + col] = fmaxf(a[g] + b1, 0.f);
    }
    __syncthreads();

#pragma unroll
    for (int g = 0; g < 8; g++) a[g] = 0.f;
#pragma unroll 4
    for (int k = 0; k < H; k++) {
        float w = __ldg(&Ws2[(size_t)k * H + col]);
#pragma unroll
        for (int g = 0; g < 8; g++) a[g] += s1[(g0 + g) * H + k] * w;
    }
    {
        float b2 = __ldg(&bs2[col]);
#pragma unroll
        for (int g = 0; g < 8; g++) {
            int gg = g0 + g;
            comb[gg * 2 * H + col] = a[g] + b2;
            float c = (float)__ldg(&cnt[b0 + gg]);
            comb[gg * 2 * H + H + col] =
                __ldg(&gsum[(size_t)(b0 + gg) * H + col]) / fmaxf(c, 1.f);
        }
    }
    __syncthreads();

#pragma unroll
    for (int g = 0; g < 8; g++) a[g] = 0.f;
#pragma unroll 4
    for (int k = 0; k < 2 * H; k++) {
        float w = __ldg(&Wf[(size_t)k * H + col]);
#pragma unroll
        for (int g = 0; g < 8; g++) a[g] += comb[(g0 + g) * 2 * H + k] * w;
    }
    {
        float bfv = __ldg(&bf[col]);
#pragma unroll
        for (int g = 0; g < 8; g++) fz[(g0 + g) * H + col] = fmaxf(a[g] + bfv, 0.f);
    }
    __syncthreads();

    if (tid < FIN_G * NC) {
        int g = tid / NC, c = tid % NC;
        float s = __ldg(&bo[c]);
        for (int k = 0; k < H; k++)
            s += fz[g * H + k] * __ldg(&Wo[(size_t)k * NC + c]);
        out[(size_t)(b0 + g) * NC + c] = s;
    }
}

// ---------------------------------------------------------------------------
extern "C" void kernel_launch(void* const* d_in, const int* in_sizes, int n_in,
                              void* d_out, int out_size) {
    const float* smiles = (const float*)d_in[0];
    const float* x      = (const float*)d_in[1];
    const int*   ei     = (const int*)d_in[2];
    const int*   batch  = (const int*)d_in[3];
    const float* Ws1 = (const float*)d_in[4];
    const float* bs1 = (const float*)d_in[5];
    const float* Ws2 = (const float*)d_in[6];
    const float* bs2 = (const float*)d_in[7];
    const float* Wg1 = (const float*)d_in[8];
    const float* bg1 = (const float*)d_in[9];
    const float* Wg2 = (const float*)d_in[10];
    const float* bg2 = (const float*)d_in[11];
    const float* Wf  = (const float*)d_in[12];
    const float* bf  = (const float*)d_in[13];
    const float* Wo  = (const float*)d_in[14];
    const float* bo  = (const float*)d_in[15];
    float* out = (float*)d_out;

    float *dinv, *gsum;
    __half *hsH, *sumH;
    int *edeg, *off, *cursor, *csr, *blocksum, *blockoff, *cnt;
    cudaGetSymbolAddress((void**)&hsH,  g_hsH);
    cudaGetSymbolAddress((void**)&sumH, g_sumH);
    cudaGetSymbolAddress((void**)&dinv, g_dinv);
    cudaGetSymbolAddress((void**)&edeg, g_edeg);
    cudaGetSymbolAddress((void**)&off,  g_off);
    cudaGetSymbolAddress((void**)&cursor, g_cursor);
    cudaGetSymbolAddress((void**)&csr,  g_csr);
    cudaGetSymbolAddress((void**)&blocksum, g_blocksum);
    cudaGetSymbolAddress((void**)&blockoff, g_blockoff);
    cudaGetSymbolAddress((void**)&gsum, g_gsum);
    cudaGetSymbolAddress((void**)&cnt,  g_cnt);

    cudaFuncSetAttribute(gemm_tc_kernel,
                         cudaFuncAttributeMaxDynamicSharedMemorySize, GEMM_SMEM);
    cudaFuncSetAttribute(final_kernel,
                         cudaFuncAttributeMaxDynamicSharedMemorySize, FIN_SMEM);

    const int* src = ei;
    const int* dst = ei + NE;

    const int T = 256;

    // --- preprocessing: degrees, counts, CSR by dst ---
    prep_zero_kernel<<<(NG * H + T - 1) / T, T>>>(edeg, cnt, gsum, off);
    count_kernel<<<(NE + T - 1) / T, T>>>(dst, batch, edeg, cnt);
    scan1_kernel<<<SCAN_NB, SCAN_B>>>(edeg, blocksum);
    scan2_kernel<<<1, SCAN_B>>>(blocksum, blockoff);
    scan3_kernel<<<SCAN_NB, SCAN_B>>>(edeg, blockoff, off, cursor, dinv);
    scatter_kernel<<<(NE + T - 1) / T, T>>>(src, dst, cursor, csr);

    const int AGG_GRID = (NN * 32 + T - 1) / T;

    // --- GCN layer 1 ---
    gemm_tc_kernel<<<GEMM_TILES, 256, GEMM_SMEM>>>(x, Wg1, dinv, bg1, hsH, NN, 0);
    agg_kernel<<<AGG_GRID, T>>>((const uint2*)hsH, off, csr, dinv, bg2, batch,
                                (uint2*)sumH, gsum, 0);

    // --- GCN layer 2 (fp16 sums in; transform relu(bg1 + dinv*sum) inside) ---
    gemm_tc_kernel<<<GEMM_TILES, 256, GEMM_SMEM>>>(sumH, Wg2, dinv, bg1, hsH, NN, 1);
    // aggregate + fused pool into gsum
    agg_kernel<<<AGG_GRID, T>>>((const uint2*)hsH, off, csr, dinv, bg2, batch,
                                (uint2*)sumH, gsum, 1);

    // --- SMILES MLP + fusion + output head ---
    final_kernel<<<NG / FIN_G, 256, FIN_SMEM>>>(smiles, Ws1, bs1, Ws2, bs2,
                                                Wf, bf, Wo, bo, gsum, cnt, out);
}

// round 16
// speedup vs baseline: 1.0930x; 1.0930x over previous
#include <cuda_runtime.h>
#include <cuda_bf16.h>
#include <cuda_fp16.h>
#include <cstdint>

// Problem constants
constexpr int NN = 50000;    // nodes
constexpr int NE = 800000;   // edges
constexpr int NG = 1024;     // graphs
constexpr int H  = 128;      // hidden / node feature dim
constexpr int DS = 768;      // smiles dim
constexpr int NC = 12;       // classes

constexpr int SCAN_B  = 256;
constexpr int SCAN_NB = (NN + SCAN_B - 1) / SCAN_B;   // 196

// Scratch (device globals; no allocation allowed)
__device__ __half g_hsH[(size_t)NN * H];   // fp16 gather table (both layers)
__device__ __half g_sumH[(size_t)NN * H];  // layer-1 aggregate sum (fp16)
__device__ float  g_dinv[NN];
__device__ int    g_edeg[NN];              // edge-only in-degree
__device__ int    g_off[NN + 1];           // CSR offsets (by dst; block-ticket order)
__device__ int    g_cursor[NN];
__device__ int    g_csr[NE];               // src ids grouped by dst
__device__ int    g_ticket;                // scan base ticket
__device__ float  g_gsum[NG * H];
__device__ int    g_cnt[NG];

// ---------------------------------------------------------------------------
// Helpers
// ---------------------------------------------------------------------------
__device__ __forceinline__ float to_tf32(float x) {
    unsigned r;  // cvt to tf32 requires a .b32 destination register
    asm("cvt.rna.tf32.f32 %0, %1;" : "=r"(r) : "f"(x));
    return __uint_as_float(r);
}
__device__ __forceinline__ void mma_tf32(float& d0, float& d1, float& d2, float& d3,
                                         float a0, float a1, float a2, float a3,
                                         float b0, float b1) {
    asm volatile(
        "mma.sync.aligned.m16n8k8.row.col.f32.tf32.tf32.f32 "
        "{%0,%1,%2,%3}, {%4,%5,%6,%7}, {%8,%9}, {%0,%1,%2,%3};"
        : "+f"(d0), "+f"(d1), "+f"(d2), "+f"(d3)
        : "r"(__float_as_uint(a0)), "r"(__float_as_uint(a1)),
          "r"(__float_as_uint(a2)), "r"(__float_as_uint(a3)),
          "r"(__float_as_uint(b0)), "r"(__float_as_uint(b1)));
}
__device__ __forceinline__ void red_add_v4(float* p, float4 v) {
    asm volatile("red.global.add.v4.f32 [%0], {%1, %2, %3, %4};"
                 :: "l"(p), "f"(v.x), "f"(v.y), "f"(v.z), "f"(v.w)
                 : "memory");
}
// Accumulate 4 halves (as uint2) into a float4 accumulator.
__device__ __forceinline__ void acc_h4(float4& a, uint2 u) {
    __half2 h0 = *reinterpret_cast<__half2*>(&u.x);
    __half2 h1 = *reinterpret_cast<__half2*>(&u.y);
    float2 f0 = __half22float2(h0);
    float2 f1 = __half22float2(h1);
    a.x += f0.x; a.y += f0.y; a.z += f1.x; a.w += f1.y;
}

// ---------------------------------------------------------------------------
// K0: zero/init
// ---------------------------------------------------------------------------
__global__ void prep_zero_kernel(int* __restrict__ edeg, int* __restrict__ cnt,
                                 float* __restrict__ gsum, int* __restrict__ ticket) {
    int i = blockIdx.x * blockDim.x + threadIdx.x;
    if (i < NN) edeg[i] = 0;
    if (i < NG) cnt[i] = 0;
    if (i < NG * H) gsum[i] = 0.0f;
    if (i == 0) *ticket = 0;
}

// ---------------------------------------------------------------------------
// K1: in-degree (edges only) + node counts per graph
// ---------------------------------------------------------------------------
__global__ void count_kernel(const int* __restrict__ dst, const int* __restrict__ batch,
                             int* __restrict__ edeg, int* __restrict__ cnt) {
    int i = blockIdx.x * blockDim.x + threadIdx.x;
    if (i < NE) atomicAdd(&edeg[dst[i]], 1);
    if (i < NN) atomicAdd(&cnt[batch[i]], 1);
}

// ---------------------------------------------------------------------------
// K2 (fused scan): per-block scan + global ticket for base; off/cursor/dinv.
// Block bases are in arbitrary (atomic) order — CSR ranges stay disjoint and
// per-node contiguous; consumers use edeg[w] for the range length.
// ---------------------------------------------------------------------------
__global__ __launch_bounds__(SCAN_B)
void scanfuse_kernel(const int* __restrict__ edeg, int* __restrict__ ticket,
                     int* __restrict__ off, int* __restrict__ cursor,
                     float* __restrict__ dinv) {
    __shared__ int wsum[8], wbase[8], sbase;
    int t = threadIdx.x;
    int lane = t & 31, wid = t >> 5;
    int i = blockIdx.x * SCAN_B + t;
    int v = (i < NN) ? edeg[i] : 0;
    int x = v;
#pragma unroll
    for (int d = 1; d < 32; d <<= 1) {
        int y = __shfl_up_sync(0xffffffff, x, d);
        if (lane >= d) x += y;
    }
    if (lane == 31) wsum[wid] = x;
    __syncthreads();
    if (t == 0) {
        int run = 0;
#pragma unroll
        for (int k = 0; k < 8; k++) { wbase[k] = run; run += wsum[k]; }
        sbase = atomicAdd(ticket, run);
    }
    __syncthreads();
    if (i < NN) {
        int e = sbase + wbase[wid] + (x - v);
        off[i] = e;
        cursor[i] = e;
        dinv[i] = rsqrtf((float)(v + 1));   // self-loop included
    }
}

// ---------------------------------------------------------------------------
// K3: scatter edges into CSR (grouped by dst)
// ---------------------------------------------------------------------------
__global__ void scatter_kernel(const int* __restrict__ src, const int* __restrict__ dst,
                               int* __restrict__ cursor, int* __restrict__ csr) {
    int i = blockIdx.x * blockDim.x + threadIdx.x;
    if (i >= NE) return;
    int d = dst[i];
    int p = atomicAdd(&cursor[d], 1);
    csr[p] = src[i];
}

// ---------------------------------------------------------------------------
// Single-wave tf32 tensor-core GEMM, 192-row tiles (one tile per CTA):
//   hsH[M,128] = fp16( dinv[row] * (T(A)[M,128] @ W[128,128]) )
//   mode 0: A is fp32; T(a) = a
//   mode 1: A is fp16 (layer-1 sums); T(a) = relu(biasIn[k] + dinv[row]*a)
// 256 thr (8 warps); warp wi owns cols wi*16..+15, 12 m-tiles of 16 rows.
// W tf32-resident [128][136]; X staged in 32-k chunks [192][36].
// ---------------------------------------------------------------------------
constexpr int TROWS = 192;
constexpr int WS_STRIDE = 136;
constexpr int XS_STRIDE = 36;
constexpr int GEMM_SMEM = 128 * WS_STRIDE * 4 + TROWS * XS_STRIDE * 4;  // 97280
constexpr int GEMM_TILES = (NN + TROWS - 1) / TROWS;      // 261

__global__ __launch_bounds__(256, 2)
void gemm_tc_kernel(const void* __restrict__ A, const float* __restrict__ W,
                    const float* __restrict__ dinv, const float* __restrict__ biasIn,
                    __half* __restrict__ outH, int M, int mode)
{
    extern __shared__ char smem_raw[];
    float* Wsm = (float*)smem_raw;                         // [128][136]
    float* Xs  = (float*)(smem_raw + 128 * WS_STRIDE * 4); // [192][36]

    const int tid  = threadIdx.x;
    const int lane = tid & 31;
    const int wi   = tid >> 5;        // warp id 0..7
    const int n0   = wi * 16;         // this warp's col base
    const int lq   = lane >> 2;       // lane/4: 0..7
    const int lr   = lane & 3;        // lane%4: 0..3

    // Stage W (tf32): 4096 float4 loads, 16 per thread.
#pragma unroll
    for (int i = 0; i < 16; i++) {
        int li = tid + i * 256;       // 0..4095
        int k  = li >> 5;             // 0..127
        int c4 = li & 31;             // 0..31
        float4 v = __ldg((const float4*)W + li);
        float* wp = Wsm + k * WS_STRIDE + c4 * 4;
        wp[0] = to_tf32(v.x); wp[1] = to_tf32(v.y);
        wp[2] = to_tf32(v.z); wp[3] = to_tf32(v.w);
    }

    for (int tile = blockIdx.x; tile < GEMM_TILES; tile += gridDim.x) {
        const int row0 = tile * TROWS;

        float acc[12][2][4];
#pragma unroll
        for (int mt = 0; mt < 12; mt++)
#pragma unroll
            for (int nt = 0; nt < 2; nt++)
#pragma unroll
                for (int c = 0; c < 4; c++) acc[mt][nt][c] = 0.0f;

        for (int chunk = 0; chunk < 4; chunk++) {
            const int k0 = chunk * 32;
            __syncthreads();   // Xs reusable / publishes W on first pass
            // Stage X chunk: 192 rows x 32 k = 1536 vec4 loads, 6/thread.
#pragma unroll
            for (int i = 0; i < 6; i++) {
                int li = tid + i * 256;    // 0..1535
                int r  = li >> 3;          // 0..191
                int c4 = li & 7;           // 0..7
                int gr = row0 + r;
                float4 v = make_float4(0.f, 0.f, 0.f, 0.f);
                if (gr < M) {
                    if (mode == 0) {
                        v = __ldg((const float4*)((const float*)A +
                                  (size_t)gr * 128 + k0) + c4);
                    } else {
                        uint2 u = __ldg((const uint2*)((const __half*)A +
                                  (size_t)gr * 128 + k0) + c4);
                        __half2 h0 = *reinterpret_cast<__half2*>(&u.x);
                        __half2 h1 = *reinterpret_cast<__half2*>(&u.y);
                        float2 f0 = __half22float2(h0);
                        float2 f1 = __half22float2(h1);
                        float di = __ldg(&dinv[gr]);
                        float4 bb = __ldg((const float4*)(biasIn + k0) + c4);
                        v.x = fmaxf(bb.x + di * f0.x, 0.f);
                        v.y = fmaxf(bb.y + di * f0.y, 0.f);
                        v.z = fmaxf(bb.z + di * f1.x, 0.f);
                        v.w = fmaxf(bb.w + di * f1.y, 0.f);
                    }
                }
                float* xr = Xs + r * XS_STRIDE + c4 * 4;
                xr[0] = to_tf32(v.x); xr[1] = to_tf32(v.y);
                xr[2] = to_tf32(v.z); xr[3] = to_tf32(v.w);
            }
            __syncthreads();

#pragma unroll
            for (int ks = 0; ks < 4; ks++) {
                const int kb = k0 + ks * 8;      // absolute k for W
                const int kx = ks * 8;           // k within X chunk
                float b[2][2];
#pragma unroll
                for (int nt = 0; nt < 2; nt++) {
                    int nc = n0 + nt * 8 + lq;
                    b[nt][0] = Wsm[(kb + lr) * WS_STRIDE + nc];
                    b[nt][1] = Wsm[(kb + 4 + lr) * WS_STRIDE + nc];
                }
#pragma unroll
                for (int mt = 0; mt < 12; mt++) {
                    int rbase = mt * 16;
                    float a0 = Xs[(rbase + lq) * XS_STRIDE + kx + lr];
                    float a1 = Xs[(rbase + lq + 8) * XS_STRIDE + kx + lr];
                    float a2 = Xs[(rbase + lq) * XS_STRIDE + kx + lr + 4];
                    float a3 = Xs[(rbase + lq + 8) * XS_STRIDE + kx + lr + 4];
                    mma_tf32(acc[mt][0][0], acc[mt][0][1], acc[mt][0][2], acc[mt][0][3],
                             a0, a1, a2, a3, b[0][0], b[0][1]);
                    mma_tf32(acc[mt][1][0], acc[mt][1][1], acc[mt][1][2], acc[mt][1][3],
                             a0, a1, a2, a3, b[1][0], b[1][1]);
                }
            }
        }

        // Epilogue: scale rows by dinv, store fp16 pairs.
#pragma unroll
        for (int mt = 0; mt < 12; mt++) {
            int r1 = row0 + mt * 16 + lq;
            int r2 = r1 + 8;
            float d1 = (r1 < M) ? __ldg(&dinv[r1]) : 0.f;
            float d2 = (r2 < M) ? __ldg(&dinv[r2]) : 0.f;
#pragma unroll
            for (int nt = 0; nt < 2; nt++) {
                int col = n0 + nt * 8 + lr * 2;
                if (r1 < M)
                    *(__half2*)(outH + (size_t)r1 * 128 + col) =
                        __floats2half2_rn(acc[mt][nt][0] * d1, acc[mt][nt][1] * d1);
                if (r2 < M)
                    *(__half2*)(outH + (size_t)r2 * 128 + col) =
                        __floats2half2_rn(acc[mt][nt][2] * d2, acc[mt][nt][3] * d2);
            }
        }
    }
}

// ---------------------------------------------------------------------------
// Aggregate: one warp per node, fp16 gather (256B/row), fp32 accumulation.
// Range = [off[w], off[w]+edeg[w]) (ticket-ordered CSR).
//   mode 0: write fp16 sum to outSum (layer-1 path; GEMM2 re-reads fp16)
//   mode 1: v = relu(bg2 + dinv[n]*sum); red_add to gsum[batch[n]]  (fused pool)
// ---------------------------------------------------------------------------
__global__ __launch_bounds__(256)
void agg_kernel(const uint2* __restrict__ hsv, const int* __restrict__ off,
                const int* __restrict__ edeg, const int* __restrict__ csr,
                const float* __restrict__ dinv, const float* __restrict__ bias,
                const int* __restrict__ batch,
                uint2* __restrict__ outSum, float* __restrict__ gsum, int mode)
{
    int w = (blockIdx.x * blockDim.x + threadIdx.x) >> 5;
    if (w >= NN) return;
    int lane = threadIdx.x & 31;
    int o0 = __ldg(&off[w]);
    int o1 = o0 + __ldg(&edeg[w]);

    float4 acc0 = make_float4(0.f, 0.f, 0.f, 0.f);
    float4 acc1 = make_float4(0.f, 0.f, 0.f, 0.f);
    acc_h4(acc0, __ldg(&hsv[(size_t)w * 32 + lane]));   // self-loop term

    int j = o0;
    for (; j + 4 <= o1; j += 4) {
        int s0 = __ldg(&csr[j]);
        int s1 = __ldg(&csr[j + 1]);
        int s2 = __ldg(&csr[j + 2]);
        int s3 = __ldg(&csr[j + 3]);
        uint2 v0 = __ldg(&hsv[(size_t)s0 * 32 + lane]);
        uint2 v1 = __ldg(&hsv[(size_t)s1 * 32 + lane]);
        uint2 v2 = __ldg(&hsv[(size_t)s2 * 32 + lane]);
        uint2 v3 = __ldg(&hsv[(size_t)s3 * 32 + lane]);
        acc_h4(acc0, v0); acc_h4(acc1, v1); acc_h4(acc0, v2); acc_h4(acc1, v3);
    }
    for (; j < o1; j++) {
        int s = __ldg(&csr[j]);
        acc_h4(acc0, __ldg(&hsv[(size_t)s * 32 + lane]));
    }
    acc0.x += acc1.x; acc0.y += acc1.y; acc0.z += acc1.z; acc0.w += acc1.w;

    if (mode == 0) {
        __half2 h0 = __floats2half2_rn(acc0.x, acc0.y);
        __half2 h1 = __floats2half2_rn(acc0.z, acc0.w);
        uint2 o;
        o.x = *reinterpret_cast<unsigned*>(&h0);
        o.y = *reinterpret_cast<unsigned*>(&h1);
        outSum[(size_t)w * 32 + lane] = o;
    } else {
        float di = __ldg(&dinv[w]);
        float4 bb = __ldg((const float4*)bias + lane);
        acc0.x = fmaxf(bb.x + di * acc0.x, 0.f);
        acc0.y = fmaxf(bb.y + di * acc0.y, 0.f);
        acc0.z = fmaxf(bb.z + di * acc0.z, 0.f);
        acc0.w = fmaxf(bb.w + di * acc0.w, 0.f);
        int b = __ldg(&batch[w]);
        red_add_v4(gsum + (size_t)b * 128 + lane * 4, acc0);
    }
}

// ---------------------------------------------------------------------------
// Fused head: 8 graphs per block, 128 threads (thread j owns output col j).
// (R14 version — 128 blocks ≈ one full wave.)
// ---------------------------------------------------------------------------
__global__ __launch_bounds__(128)
void final_kernel(const float* __restrict__ smiles,
                  const float* __restrict__ Ws1, const float* __restrict__ bs1,
                  const float* __restrict__ Ws2, const float* __restrict__ bs2,
                  const float* __restrict__ Wf,  const float* __restrict__ bf,
                  const float* __restrict__ Wo,  const float* __restrict__ bo,
                  const float* __restrict__ gsum, const int* __restrict__ cnt,
                  float* __restrict__ out) {
    __shared__ float sm[8][DS];
    __shared__ float s1[8][H];
    __shared__ float comb[8][2 * H];
    __shared__ float fz[8][H];

    const int b0 = blockIdx.x * 8;
    const int j = threadIdx.x;

    const float4* sp = (const float4*)(smiles + (size_t)b0 * DS);
#pragma unroll
    for (int i = 0; i < 12; i++)
        ((float4*)sm)[j + i * 128] = __ldg(sp + j + i * 128);
    __syncthreads();

    float a[8];
#pragma unroll
    for (int g = 0; g < 8; g++) a[g] = 0.f;
#pragma unroll 4
    for (int k = 0; k < DS; k++) {
        float w = __ldg(&Ws1[(size_t)k * H + j]);
#pragma unroll
        for (int g = 0; g < 8; g++) a[g] += sm[g][k] * w;
    }
    {
        float b1 = __ldg(&bs1[j]);
#pragma unroll
        for (int g = 0; g < 8; g++) s1[g][j] = fmaxf(a[g] + b1, 0.f);
    }
    __syncthreads();

#pragma unroll
    for (int g = 0; g < 8; g++) a[g] = 0.f;
#pragma unroll 4
    for (int k = 0; k < H; k++) {
        float w = __ldg(&Ws2[(size_t)k * H + j]);
#pragma unroll
        for (int g = 0; g < 8; g++) a[g] += s1[g][k] * w;
    }
    {
        float b2 = __ldg(&bs2[j]);
#pragma unroll
        for (int g = 0; g < 8; g++) {
            comb[g][j] = a[g] + b2;
            float c = (float)__ldg(&cnt[b0 + g]);
            comb[g][H + j] = __ldg(&gsum[(size_t)(b0 + g) * H + j]) / fmaxf(c, 1.f);
        }
    }
    __syncthreads();

#pragma unroll
    for (int g = 0; g < 8; g++) a[g] = 0.f;
#pragma unroll 4
    for (int k = 0; k < 2 * H; k++) {
        float w = __ldg(&Wf[(size_t)k * H + j]);
#pragma unroll
        for (int g = 0; g < 8; g++) a[g] += comb[g][k] * w;
    }
    {
        float bfv = __ldg(&bf[j]);
#pragma unroll
        for (int g = 0; g < 8; g++) fz[g][j] = fmaxf(a[g] + bfv, 0.f);
    }
    __syncthreads();

    if (j < 8 * NC) {
        int g = j / NC, c = j % NC;
        float s = __ldg(&bo[c]);
        for (int k = 0; k < H; k++)
            s += fz[g][k] * __ldg(&Wo[(size_t)k * NC + c]);
        out[(size_t)(b0 + g) * NC + c] = s;
    }
}

// ---------------------------------------------------------------------------
extern "C" void kernel_launch(void* const* d_in, const int* in_sizes, int n_in,
                              void* d_out, int out_size) {
    const float* smiles = (const float*)d_in[0];
    const float* x      = (const float*)d_in[1];
    const int*   ei     = (const int*)d_in[2];
    const int*   batch  = (const int*)d_in[3];
    const float* Ws1 = (const float*)d_in[4];
    const float* bs1 = (const float*)d_in[5];
    const float* Ws2 = (const float*)d_in[6];
    const float* bs2 = (const float*)d_in[7];
    const float* Wg1 = (const float*)d_in[8];
    const float* bg1 = (const float*)d_in[9];
    const float* Wg2 = (const float*)d_in[10];
    const float* bg2 = (const float*)d_in[11];
    const float* Wf  = (const float*)d_in[12];
    const float* bf  = (const float*)d_in[13];
    const float* Wo  = (const float*)d_in[14];
    const float* bo  = (const float*)d_in[15];
    float* out = (float*)d_out;

    float *dinv, *gsum;
    __half *hsH, *sumH;
    int *edeg, *off, *cursor, *csr, *ticket, *cnt;
    cudaGetSymbolAddress((void**)&hsH,  g_hsH);
    cudaGetSymbolAddress((void**)&sumH, g_sumH);
    cudaGetSymbolAddress((void**)&dinv, g_dinv);
    cudaGetSymbolAddress((void**)&edeg, g_edeg);
    cudaGetSymbolAddress((void**)&off,  g_off);
    cudaGetSymbolAddress((void**)&cursor, g_cursor);
    cudaGetSymbolAddress((void**)&csr,  g_csr);
    cudaGetSymbolAddress((void**)&ticket, g_ticket);
    cudaGetSymbolAddress((void**)&gsum, g_gsum);
    cudaGetSymbolAddress((void**)&cnt,  g_cnt);

    cudaFuncSetAttribute(gemm_tc_kernel,
                         cudaFuncAttributeMaxDynamicSharedMemorySize, GEMM_SMEM);

    const int* src = ei;
    const int* dst = ei + NE;

    const int T = 256;

    // --- preprocessing: degrees, counts, CSR by dst (ticket-ordered) ---
    prep_zero_kernel<<<(NG * H + T - 1) / T, T>>>(edeg, cnt, gsum, ticket);
    count_kernel<<<(NE + T - 1) / T, T>>>(dst, batch, edeg, cnt);
    scanfuse_kernel<<<SCAN_NB, SCAN_B>>>(edeg, ticket, off, cursor, dinv);
    scatter_kernel<<<(NE + T - 1) / T, T>>>(src, dst, cursor, csr);

    const int AGG_GRID = (NN * 32 + T - 1) / T;

    // --- GCN layer 1 ---
    gemm_tc_kernel<<<GEMM_TILES, 256, GEMM_SMEM>>>(x, Wg1, dinv, bg1, hsH, NN, 0);
    agg_kernel<<<AGG_GRID, T>>>((const uint2*)hsH, off, edeg, csr, dinv, bg2, batch,
                                (uint2*)sumH, gsum, 0);

    // --- GCN layer 2 (fp16 sums in; transform relu(bg1 + dinv*sum) inside) ---
    gemm_tc_kernel<<<GEMM_TILES, 256, GEMM_SMEM>>>(sumH, Wg2, dinv, bg1, hsH, NN, 1);
    // aggregate + fused pool into gsum
    agg_kernel<<<AGG_GRID, T>>>((const uint2*)hsH, off, edeg, csr, dinv, bg2, batch,
                                (uint2*)sumH, gsum, 1);

    // --- SMILES MLP + fusion + output head ---
    final_kernel<<<NG / 8, 128>>>(smiles, Ws1, bs1, Ws2, bs2, Wf, bf, Wo, bo,
                                  gsum, cnt, out);
}